// round 15
// baseline (speedup 1.0000x reference)
#include <cuda_runtime.h>
#include <math.h>
#include <stdint.h>

// Problem shape constants
#define SEQ_FULL 13
#define SEQ_GEO  12
#define VOCAB    33   // GEO_VOCAB + 1
#define IGNORE   32   // V - 1

#define GRID1    740          // 148 SMs * 5 resident blocks (smem-limited)
#define THREADS1 256
#define WARPS1   8
#define TILE_ROWS 16
#define TILE_B   2112         // 16 rows * 33 floats * 4B
#define DYN_SMEM (2 * WARPS1 * TILE_B)   // double-buffered: 33792 B

// Per-block partials (SoA): 0=mask_ce 1=valid_cnt 2=correct 3=error 4=prefix
__device__ double g_p[5][GRID1];
__device__ unsigned int g_ticket;   // zero-init; reset by last block each run

__constant__ float c_cw[SEQ_GEO] = {
    1.0f, 0.8f, 0.64f, 0.512f, 0.4096f, 0.32768f,
    0.262144f, 0.2097152f, 0.16777216f, 0.134217728f,
    0.1073741824f, 0.08589934592f
};

// CONT_REWARDS closed form (== reference Riemann sum; validated 1.3e-7)
__device__ __forceinline__ float cont_reward(int idx) {
    if (idx <= 0) return 0.0f;
    double b    = (double)idx;
    double ln08 = log(0.8);
    double r    = exp(ln08 * (b / 1999.0));
    double rN   = exp(ln08 * (b * 2000.0 / 1999.0));
    double dx   = b / 2000.0;
    return (float)(1.0 / (dx * (1.0 - rN) / (1.0 - r)));
}

#define CP_ASYNC16(dst, src) \
    asm volatile("cp.async.cg.shared.global [%0], [%1], 16;" :: "r"(dst), "l"(src))
#define CP_COMMIT() asm volatile("cp.async.commit_group;")
#define CP_WAIT1()  asm volatile("cp.async.wait_group 1;")

// ---------------------------------------------------------------------------
// Single fused kernel. This round: 16-row tiles, TWO lanes per row
// (lane pair = halves of the 33 logits, one shfl_xor(16) combine), halving
// per-warp smem -> 5 blocks/SM, 40 warps/SM for latency hiding.
// Jobs: mask job = 1 subtile (16 rows); geo job = 6 subtiles (96 rows = 8
// whole batches, so prefix/argmin stays warp-local via s_pf strip).
// Last block (ticket) combines per-block partials and writes the 5 outputs.
// ---------------------------------------------------------------------------
__global__ void __launch_bounds__(THREADS1) fused_kernel(
    const float* __restrict__ geo,  const float* __restrict__ maskx,
    const int*   __restrict__ pos,  const int*   __restrict__ mgt,
    int maskRows, int B, int nMaskJobs, int nGeoJobs, int nJobs,
    const float* __restrict__ aux,  const float* __restrict__ taux,
    const float* __restrict__ sigma, float* __restrict__ out)
{
    extern __shared__ float s_dyn[];      // [8 warps][2 buffers][528 floats]
    __shared__ float  s_pf[WARPS1][96];   // packed +-ce per geo job
    __shared__ float  s_cont[SEQ_GEO];
    __shared__ double s_red[WARPS1][5];
    __shared__ bool   s_last;

    const uint32_t sbase = (uint32_t)__cvta_generic_to_shared(s_dyn);
    const int tid  = threadIdx.x;
    const int lane = tid & 31;
    const int wib  = tid >> 5;
    const int r    = lane & 15;       // row within tile
    const int h    = lane >> 4;       // half: 0 -> elems [0,16), 1 -> [16,33)
    const int gwarp = blockIdx.x * WARPS1 + wib;
    const int nwarp = gridDim.x * WARPS1;

    if (tid < SEQ_GEO) s_cont[tid] = cont_reward(tid);
    __syncthreads();

    float a_mask = 0.0f, a_cnt = 0.0f, a_cor = 0.0f, a_err = 0.0f, a_pre = 0.0f;

    // issue cp.asyncs for (job, sub) into buffer bsel; empty commit if done
    auto issue = [&](int job, int sub, int bsel) {
        if (job < nJobs) {
            const char* src = (job < nMaskJobs)
                ? (const char*)maskx + (size_t)job * TILE_B
                : (const char*)geo + ((size_t)(job - nMaskJobs) * 6 + sub) * TILE_B;
            const uint32_t dst = sbase + (uint32_t)(wib * 2 + bsel) * TILE_B;
            #pragma unroll
            for (int i = 0; i < 4; i++)
                CP_ASYNC16(dst + lane * 16 + i * 512, src + lane * 16 + i * 512);
            if (lane < 4)
                CP_ASYNC16(dst + 2048 + lane * 16, src + 2048 + lane * 16);
        }
        CP_COMMIT();
    };

    int cjob = gwarp, csub = 0;     // current cursor
    int pjob = gwarp, psub = 0;     // prefetch cursor
    issue(pjob, psub, 0);
    { int nt = (pjob < nMaskJobs) ? 1 : 6;
      if (++psub == nt) { psub = 0; pjob += nwarp; } }
    int buf = 0;

    while (cjob < nJobs) {
        issue(pjob, psub, buf ^ 1);               // prefetch next tile
        { int nt = (pjob < nMaskJobs) ? 1 : 6;
          if (++psub == nt) { psub = 0; pjob += nwarp; } }
        CP_WAIT1();                               // current tile landed
        __syncwarp();

        const float* row = s_dyn + (wib * 2 + buf) * (TILE_B / 4) + r * 33;
        const float* q   = row + (h << 4);        // this lane's 16/17 elems

        if (cjob < nMaskJobs) {
            // ---- mask tile: global row = cjob*16 + r ----
            int t = 0;
            if (h == 0) t = mgt[cjob * TILE_ROWS + r];   // hoisted
            float s0 = 0.0f, s1 = 0.0f, s2 = 0.0f, s3 = 0.0f;
            #pragma unroll
            for (int c = 0; c < 16; c += 4) {
                s0 += __expf(q[c]);     s1 += __expf(q[c + 1]);
                s2 += __expf(q[c + 2]); s3 += __expf(q[c + 3]);
            }
            float sum = (s0 + s1) + (s2 + s3);
            if (h) sum += __expf(row[32]);
            sum += __shfl_xor_sync(0xffffffffu, sum, 16);
            if (h == 0 && t != -100) {
                int tc = min(max(t, 0), VOCAB - 1);
                a_mask += __logf(sum) - row[tc];
                a_cnt  += 1.0f;
            }
        } else {
            // ---- geo tile: job g, local row lr in [0,96) ----
            const int g  = cjob - nMaskJobs;
            const int lr = csub * TILE_ROWS + r;
            int t = 0;
            if (h == 0) {
                const int bl = lr / 12;
                const int s  = lr - bl * 12;
                t = pos[(g * 8 + bl) * SEQ_FULL + s + 1];   // in [0,32]
            }
            float s0 = 0.0f, s1 = 0.0f, s2 = 0.0f, s3 = 0.0f;
            float m0 = -3.4e38f, m1 = -3.4e38f;
            #pragma unroll
            for (int c = 0; c < 16; c += 4) {
                float v0 = q[c],     v1 = q[c + 1];
                float v2 = q[c + 2], v3 = q[c + 3];
                m0 = fmaxf(m0, fmaxf(v0, v1));
                m1 = fmaxf(m1, fmaxf(v2, v3));
                s0 += __expf(v0); s1 += __expf(v1);
                s2 += __expf(v2); s3 += __expf(v3);
            }
            float sum = (s0 + s1) + (s2 + s3);
            float mv  = fmaxf(m0, m1);
            if (h) { float v32 = row[32]; sum += __expf(v32); mv = fmaxf(mv, v32); }
            sum += __shfl_xor_sync(0xffffffffu, sum, 16);
            mv   = fmaxf(mv, __shfl_xor_sync(0xffffffffu, mv, 16));
            if (h == 0) {
                float xt = row[t];
                // correct <=> target holds the row maximum (== argmax==t except
                // on exact float ties; measure-zero here, validated passing)
                bool  correct = (xt == mv);
                float ce = (t == IGNORE) ? 0.0f : (__logf(sum) - xt);
                const int s = lr - (lr / 12) * 12;
                float cw = c_cw[s];
                if (correct) a_cor += ce * cw;
                else         a_err += ce * (cw + 1.0f);
                // pack: sign bit set when incorrect (ce >= 0 always; +-0 OK)
                s_pf[wib][lr] = __uint_as_float(__float_as_uint(ce) ^
                                                (correct ? 0u : 0x80000000u));
            }
        }
        __syncwarp();

        // geo job completed -> lanes 0..7 fold their batch's prefix term
        if (cjob >= nMaskJobs && csub == 5 && lane < 8) {
            const float* pf = &s_pf[wib][lane * 12];
            int firstbad = -1; float pacc = 0.0f;
            #pragma unroll
            for (int s = 0; s < SEQ_GEO; s++) {
                float v = pf[s];
                bool corr = ((__float_as_uint(v) >> 31) == 0u);
                if (firstbad < 0) {
                    if (corr) pacc += fabsf(v);
                    else      firstbad = s;
                }
            }
            if (firstbad >= 1) a_pre += pacc * s_cont[firstbad];
        }

        buf ^= 1;
        { int nt = (cjob < nMaskJobs) ? 1 : 6;
          if (++csub == nt) { csub = 0; cjob += nwarp; } }
    }

    // ---- tails (block 0 only; empty for the dataset shape) ----
    if (blockIdx.x == 0) {
        if (wib == 0) {
            int row = nMaskJobs * TILE_ROWS + lane;   // <=15 leftover mask rows
            if (row < maskRows) {
                const float* pr = maskx + (size_t)row * VOCAB;
                float sum = 0.0f;
                #pragma unroll
                for (int c = 0; c < VOCAB; c++) sum += __expf(pr[c]);
                int t = mgt[row];
                if (t != -100) {
                    int tc = min(max(t, 0), VOCAB - 1);
                    a_mask += __logf(sum) - pr[tc];
                    a_cnt  += 1.0f;
                }
            }
        } else if (wib == 1) {
            int b = nGeoJobs * 8 + lane;              // <=7 leftover batches
            if (b < B) {
                int firstbad = -1; float pacc = 0.0f;
                for (int s = 0; s < SEQ_GEO; s++) {
                    const float* pr = geo + ((size_t)b * SEQ_GEO + s) * VOCAB;
                    float sum = 0.0f, mv = -3.4e38f;
                    for (int c = 0; c < VOCAB; c++) {
                        float v = pr[c];
                        sum += __expf(v);
                        mv = fmaxf(mv, v);
                    }
                    int t  = pos[b * SEQ_FULL + s + 1];
                    float xt = pr[min(max(t, 0), VOCAB - 1)];
                    float ce = (t == IGNORE) ? 0.0f : (__logf(sum) - xt);
                    bool correct = (xt == mv);
                    float cw = c_cw[s];
                    if (correct) a_cor += ce * cw;
                    else         a_err += ce * (cw + 1.0f);
                    if (firstbad < 0) {
                        if (correct) pacc += ce;
                        else         firstbad = s;
                    }
                }
                if (firstbad >= 1) a_pre += pacc * s_cont[firstbad];
            }
        }
    }

    // ---- block reduction -> per-block partials ----
    #pragma unroll
    for (int o = 16; o; o >>= 1) {
        a_mask += __shfl_xor_sync(0xffffffffu, a_mask, o);
        a_cnt  += __shfl_xor_sync(0xffffffffu, a_cnt,  o);
        a_cor  += __shfl_xor_sync(0xffffffffu, a_cor,  o);
        a_err  += __shfl_xor_sync(0xffffffffu, a_err,  o);
        a_pre  += __shfl_xor_sync(0xffffffffu, a_pre,  o);
    }
    if (lane == 0) {
        s_red[wib][0] = (double)a_mask; s_red[wib][1] = (double)a_cnt;
        s_red[wib][2] = (double)a_cor;  s_red[wib][3] = (double)a_err;
        s_red[wib][4] = (double)a_pre;
    }
    __syncthreads();
    if (tid == 0) {
        double t0 = 0, t1 = 0, t2 = 0, t3 = 0, t4 = 0;
        for (int i = 0; i < WARPS1; i++) {
            t0 += s_red[i][0]; t1 += s_red[i][1]; t2 += s_red[i][2];
            t3 += s_red[i][3]; t4 += s_red[i][4];
        }
        g_p[0][blockIdx.x] = t0; g_p[1][blockIdx.x] = t1;
        g_p[2][blockIdx.x] = t2; g_p[3][blockIdx.x] = t3;
        g_p[4][blockIdx.x] = t4;
        __threadfence();
        unsigned tk = atomicAdd(&g_ticket, 1u);
        s_last = (tk == gridDim.x - 1);
    }
    __syncthreads();
    if (!s_last) return;

    // ---- last block: global combine + output ----
    __shared__ double s_tot[5];
    if (wib < 5) {
        double s = 0.0;
        for (int i = lane; i < (int)gridDim.x; i += 32) s += g_p[wib][i];
        #pragma unroll
        for (int o = 16; o; o >>= 1) s += __shfl_xor_sync(0xffffffffu, s, o);
        if (lane == 0) s_tot[wib] = s;
    }
    __syncthreads();
    if (tid == 0) {
        double nm      = (double)B * (double)SEQ_GEO;
        double prefix  = s_tot[4] / nm;
        double correct = s_tot[2] / nm;
        double error   = s_tot[3] / nm;
        double maskl   = s_tot[0] / fmax(s_tot[1], 1.0);
        double geoL    = prefix + correct + error;

        double losses[4] = { geoL, maskl, (double)aux[0], (double)taux[0] };
        double wsum = 0.0, prod = 1.0;
        for (int i = 0; i < 4; i++) {
            double sg = (double)sigma[i];
            wsum += 0.5 * losses[i] / (sg * sg);
            prod *= sg;
        }
        wsum += log(prod);

        out[0] = (float)wsum;
        out[1] = (float)prefix;
        out[2] = (float)correct;
        out[3] = (float)error;
        out[4] = (float)maskl;

        g_ticket = 0;   // reset for graph replay
    }
}

// ---------------------------------------------------------------------------
// Launch.  Inputs (metadata order):
//  0 geo_output f32 (B,12,33)  1 mask_geo_output f32 (B,13,33)
//  2 pos_geo_code i32 (B,13)   3 mask_ground_truth i32 (B,13)
//  4 aux f32 ()  5 token_aux f32 ()  6 sigma f32 (4,)   Output: f32 (5,)
// ---------------------------------------------------------------------------
extern "C" void kernel_launch(void* const* d_in, const int* in_sizes, int n_in,
                              void* d_out, int out_size)
{
    const float* geo   = (const float*)d_in[0];
    const float* maskx = (const float*)d_in[1];
    const int*   pos   = (const int*)d_in[2];
    const int*   mgt   = (const int*)d_in[3];
    const float* aux   = (const float*)d_in[4];
    const float* taux  = (const float*)d_in[5];
    const float* sigma = (const float*)d_in[6];
    float* out = (float*)d_out;

    const int B        = in_sizes[0] / (SEQ_GEO * VOCAB);
    const int maskRows = B * SEQ_FULL;
    const int geoRows  = B * SEQ_GEO;

    const int nMaskJobs = maskRows / TILE_ROWS;   // 16-row subtiles
    const int nGeoJobs  = geoRows / 96;           // 96-row (8-batch) jobs
    const int nJobs     = nMaskJobs + nGeoJobs;

    cudaFuncSetAttribute(fused_kernel,
                         cudaFuncAttributeMaxDynamicSharedMemorySize, DYN_SMEM);

    fused_kernel<<<GRID1, THREADS1, DYN_SMEM>>>(
        geo, maskx, pos, mgt, maskRows, B, nMaskJobs, nGeoJobs, nJobs,
        aux, taux, sigma, out);
}

// round 16
// speedup vs baseline: 1.0346x; 1.0346x over previous
#include <cuda_runtime.h>
#include <math.h>
#include <stdint.h>

// Problem shape constants
#define SEQ_FULL 13
#define SEQ_GEO  12
#define VOCAB    33   // GEO_VOCAB + 1
#define IGNORE   32   // V - 1

#define GRID1    296          // 148 SMs * 2 resident blocks (smem-limited)
#define THREADS1 256
#define WARPS1   8
#define TILE_ROWS 32
#define TILE_B   4224         // 32 rows * 33 floats * 4B
#define NBUF     3
#define DYN_SMEM (NBUF * WARPS1 * TILE_B)   // 3-deep ring: 101376 B

// Per-block partials (SoA): 0=mask_ce 1=valid_cnt 2=correct 3=error 4=prefix
__device__ double g_p[5][GRID1];
__device__ unsigned int g_ticket;   // zero-init; reset by last block each run

__constant__ float c_cw[SEQ_GEO] = {
    1.0f, 0.8f, 0.64f, 0.512f, 0.4096f, 0.32768f,
    0.262144f, 0.2097152f, 0.16777216f, 0.134217728f,
    0.1073741824f, 0.08589934592f
};

// CONT_REWARDS closed form (== reference Riemann sum; validated 1.3e-7)
__device__ __forceinline__ float cont_reward(int idx) {
    if (idx <= 0) return 0.0f;
    double b    = (double)idx;
    double ln08 = log(0.8);
    double r    = exp(ln08 * (b / 1999.0));
    double rN   = exp(ln08 * (b * 2000.0 / 1999.0));
    double dx   = b / 2000.0;
    return (float)(1.0 / (dx * (1.0 - rN) / (1.0 - r)));
}

#define CP_ASYNC16(dst, src) \
    asm volatile("cp.async.cg.shared.global [%0], [%1], 16;" :: "r"(dst), "l"(src))
#define CP_COMMIT() asm volatile("cp.async.commit_group;")
#define CP_WAIT2()  asm volatile("cp.async.wait_group 2;")

// ---------------------------------------------------------------------------
// Single fused kernel. This round: DEPTH-2 prefetch (3-buffer ring per warp,
// wait_group 2) so the tile being consumed was issued two iterations ago and
// has already drained the DRAM queue -> wait is ~free, round ~= DRAM drain.
// 32-row tiles, lane-per-row (R14's trimmed compute). 16 warps/SM.
// Jobs: mask job = 1 tile; geo job = 3 tiles (96 rows = 8 whole batches).
// Last block (ticket) combines per-block partials and writes the 5 outputs.
// ---------------------------------------------------------------------------
__global__ void __launch_bounds__(THREADS1) fused_kernel(
    const float* __restrict__ geo,  const float* __restrict__ maskx,
    const int*   __restrict__ pos,  const int*   __restrict__ mgt,
    int maskRows, int B, int nMaskJobs, int nGeoJobs, int nJobs,
    const float* __restrict__ aux,  const float* __restrict__ taux,
    const float* __restrict__ sigma, float* __restrict__ out)
{
    extern __shared__ float s_dyn[];      // [8 warps][3 buffers][1056 floats]
    __shared__ float  s_pf[WARPS1][96];   // packed +-ce per geo job
    __shared__ float  s_cont[SEQ_GEO];
    __shared__ double s_red[WARPS1][5];
    __shared__ bool   s_last;

    const uint32_t sbase = (uint32_t)__cvta_generic_to_shared(s_dyn);
    const int tid  = threadIdx.x;
    const int lane = tid & 31;
    const int wib  = tid >> 5;
    const int gwarp = blockIdx.x * WARPS1 + wib;
    const int nwarp = gridDim.x * WARPS1;

    if (tid < SEQ_GEO) s_cont[tid] = cont_reward(tid);
    __syncthreads();

    float a_mask = 0.0f, a_cnt = 0.0f, a_cor = 0.0f, a_err = 0.0f, a_pre = 0.0f;

    // issue cp.asyncs for (job, sub) into ring slot bsel; empty commit if done
    auto issue = [&](int job, int sub, int bsel) {
        if (job < nJobs) {
            const char* src = (job < nMaskJobs)
                ? (const char*)maskx + (size_t)job * TILE_B
                : (const char*)geo + ((size_t)(job - nMaskJobs) * 3 + sub) * TILE_B;
            const uint32_t dst = sbase + (uint32_t)(wib * NBUF + bsel) * TILE_B;
            #pragma unroll
            for (int i = 0; i < 8; i++)
                CP_ASYNC16(dst + lane * 16 + i * 512, src + lane * 16 + i * 512);
            if (lane < 8)
                CP_ASYNC16(dst + 4096 + lane * 16, src + 4096 + lane * 16);
        }
        CP_COMMIT();
    };
    auto adv = [&](int& job, int& sub) {
        int nt = (job < nMaskJobs) ? 1 : 3;
        if (++sub == nt) { sub = 0; job += nwarp; }
    };

    int cjob = gwarp, csub = 0;     // current cursor
    int pjob = gwarp, psub = 0;     // prefetch cursor
    issue(pjob, psub, 0); adv(pjob, psub);   // depth-2 prologue
    issue(pjob, psub, 1); adv(pjob, psub);
    int buf = 0;

    while (cjob < nJobs) {
        // issue tile n+2 into slot (buf+2)%3, then drain tile n (issued 2 ago)
        int nslot = buf + 2; if (nslot >= NBUF) nslot -= NBUF;
        issue(pjob, psub, nslot); adv(pjob, psub);
        CP_WAIT2();
        __syncwarp();

        const float* r = s_dyn + (wib * NBUF + buf) * (TILE_B / 4) + lane * 33;

        if (cjob < nMaskJobs) {
            // ---- mask tile: row = cjob*32 + lane ----
            const int row = cjob * TILE_ROWS + lane;
            const int t   = mgt[row];             // hoisted: overlaps exp chain
            float s0 = 0.0f, s1 = 0.0f, s2 = 0.0f, s3 = 0.0f;
            #pragma unroll
            for (int c = 0; c < 32; c += 4) {
                s0 += __expf(r[c]);
                s1 += __expf(r[c + 1]);
                s2 += __expf(r[c + 2]);
                s3 += __expf(r[c + 3]);
            }
            float sum = ((s0 + s1) + (s2 + s3)) + __expf(r[32]);
            if (t != -100) {
                int tc = min(max(t, 0), VOCAB - 1);
                a_mask += __logf(sum) - r[tc];
                a_cnt  += 1.0f;
            }
        } else {
            // ---- geo tile: job g, local row lr in [0,96) ----
            const int g  = cjob - nMaskJobs;
            const int lr = csub * TILE_ROWS + lane;
            const int bl = lr / 12;               // local batch 0..7
            const int s  = lr - bl * 12;
            const int t  = pos[(g * 8 + bl) * SEQ_FULL + s + 1];   // in [0,32]

            float s0 = 0.0f, s1 = 0.0f, s2 = 0.0f, s3 = 0.0f;
            float m0 = -3.4e38f, m1 = -3.4e38f;
            #pragma unroll
            for (int c = 0; c < 32; c += 4) {
                float v0 = r[c],     v1 = r[c + 1];
                float v2 = r[c + 2], v3 = r[c + 3];
                m0 = fmaxf(m0, fmaxf(v0, v1));
                m1 = fmaxf(m1, fmaxf(v2, v3));
                s0 += __expf(v0); s1 += __expf(v1);
                s2 += __expf(v2); s3 += __expf(v3);
            }
            float v32 = r[32];
            float mv  = fmaxf(fmaxf(m0, m1), v32);
            float sum = ((s0 + s1) + (s2 + s3)) + __expf(v32);
            float xt  = r[t];
            // correct <=> target holds the row maximum (== argmax==t except on
            // exact float ties; measure-zero here, validated passing)
            bool  correct = (xt == mv);
            float ce = (t == IGNORE) ? 0.0f : (__logf(sum) - xt);
            float cw = c_cw[s];
            if (correct) a_cor += ce * cw;
            else         a_err += ce * (cw + 1.0f);
            // pack: sign bit set when incorrect (ce >= 0 always; +-0 OK)
            s_pf[wib][lr] = __uint_as_float(__float_as_uint(ce) ^
                                            (correct ? 0u : 0x80000000u));
        }
        __syncwarp();

        // geo job completed -> lanes 0..7 fold their batch's prefix term
        if (cjob >= nMaskJobs && csub == 2 && lane < 8) {
            const float* pf = &s_pf[wib][lane * 12];
            int firstbad = -1; float pacc = 0.0f;
            #pragma unroll
            for (int s = 0; s < SEQ_GEO; s++) {
                float v = pf[s];
                bool corr = ((__float_as_uint(v) >> 31) == 0u);
                if (firstbad < 0) {
                    if (corr) pacc += fabsf(v);
                    else      firstbad = s;
                }
            }
            if (firstbad >= 1) a_pre += pacc * s_cont[firstbad];
        }

        if (++buf >= NBUF) buf = 0;
        adv(cjob, csub);
    }

    // ---- tails (block 0 only; empty for the dataset shape) ----
    if (blockIdx.x == 0) {
        if (wib == 0) {
            int row = nMaskJobs * TILE_ROWS + lane;   // <=31 leftover mask rows
            if (row < maskRows) {
                const float* pr = maskx + (size_t)row * VOCAB;
                float sum = 0.0f;
                #pragma unroll
                for (int c = 0; c < VOCAB; c++) sum += __expf(pr[c]);
                int t = mgt[row];
                if (t != -100) {
                    int tc = min(max(t, 0), VOCAB - 1);
                    a_mask += __logf(sum) - pr[tc];
                    a_cnt  += 1.0f;
                }
            }
        } else if (wib == 1) {
            int b = nGeoJobs * 8 + lane;              // <=7 leftover batches
            if (b < B) {
                int firstbad = -1; float pacc = 0.0f;
                for (int s = 0; s < SEQ_GEO; s++) {
                    const float* pr = geo + ((size_t)b * SEQ_GEO + s) * VOCAB;
                    float sum = 0.0f, mv = -3.4e38f;
                    for (int c = 0; c < VOCAB; c++) {
                        float v = pr[c];
                        sum += __expf(v);
                        mv = fmaxf(mv, v);
                    }
                    int t  = pos[b * SEQ_FULL + s + 1];
                    float xt = pr[min(max(t, 0), VOCAB - 1)];
                    float ce = (t == IGNORE) ? 0.0f : (__logf(sum) - xt);
                    bool correct = (xt == mv);
                    float cw = c_cw[s];
                    if (correct) a_cor += ce * cw;
                    else         a_err += ce * (cw + 1.0f);
                    if (firstbad < 0) {
                        if (correct) pacc += ce;
                        else         firstbad = s;
                    }
                }
                if (firstbad >= 1) a_pre += pacc * s_cont[firstbad];
            }
        }
    }

    // ---- block reduction -> per-block partials ----
    #pragma unroll
    for (int o = 16; o; o >>= 1) {
        a_mask += __shfl_xor_sync(0xffffffffu, a_mask, o);
        a_cnt  += __shfl_xor_sync(0xffffffffu, a_cnt,  o);
        a_cor  += __shfl_xor_sync(0xffffffffu, a_cor,  o);
        a_err  += __shfl_xor_sync(0xffffffffu, a_err,  o);
        a_pre  += __shfl_xor_sync(0xffffffffu, a_pre,  o);
    }
    if (lane == 0) {
        s_red[wib][0] = (double)a_mask; s_red[wib][1] = (double)a_cnt;
        s_red[wib][2] = (double)a_cor;  s_red[wib][3] = (double)a_err;
        s_red[wib][4] = (double)a_pre;
    }
    __syncthreads();
    if (tid == 0) {
        double t0 = 0, t1 = 0, t2 = 0, t3 = 0, t4 = 0;
        for (int i = 0; i < WARPS1; i++) {
            t0 += s_red[i][0]; t1 += s_red[i][1]; t2 += s_red[i][2];
            t3 += s_red[i][3]; t4 += s_red[i][4];
        }
        g_p[0][blockIdx.x] = t0; g_p[1][blockIdx.x] = t1;
        g_p[2][blockIdx.x] = t2; g_p[3][blockIdx.x] = t3;
        g_p[4][blockIdx.x] = t4;
        __threadfence();
        unsigned tk = atomicAdd(&g_ticket, 1u);
        s_last = (tk == gridDim.x - 1);
    }
    __syncthreads();
    if (!s_last) return;

    // ---- last block: global combine + output ----
    __shared__ double s_tot[5];
    if (wib < 5) {
        double s = 0.0;
        for (int i = lane; i < (int)gridDim.x; i += 32) s += g_p[wib][i];
        #pragma unroll
        for (int o = 16; o; o >>= 1) s += __shfl_xor_sync(0xffffffffu, s, o);
        if (lane == 0) s_tot[wib] = s;
    }
    __syncthreads();
    if (tid == 0) {
        double nm      = (double)B * (double)SEQ_GEO;
        double prefix  = s_tot[4] / nm;
        double correct = s_tot[2] / nm;
        double error   = s_tot[3] / nm;
        double maskl   = s_tot[0] / fmax(s_tot[1], 1.0);
        double geoL    = prefix + correct + error;

        double losses[4] = { geoL, maskl, (double)aux[0], (double)taux[0] };
        double wsum = 0.0, prod = 1.0;
        for (int i = 0; i < 4; i++) {
            double sg = (double)sigma[i];
            wsum += 0.5 * losses[i] / (sg * sg);
            prod *= sg;
        }
        wsum += log(prod);

        out[0] = (float)wsum;
        out[1] = (float)prefix;
        out[2] = (float)correct;
        out[3] = (float)error;
        out[4] = (float)maskl;

        g_ticket = 0;   // reset for graph replay
    }
}

// ---------------------------------------------------------------------------
// Launch.  Inputs (metadata order):
//  0 geo_output f32 (B,12,33)  1 mask_geo_output f32 (B,13,33)
//  2 pos_geo_code i32 (B,13)   3 mask_ground_truth i32 (B,13)
//  4 aux f32 ()  5 token_aux f32 ()  6 sigma f32 (4,)   Output: f32 (5,)
// ---------------------------------------------------------------------------
extern "C" void kernel_launch(void* const* d_in, const int* in_sizes, int n_in,
                              void* d_out, int out_size)
{
    const float* geo   = (const float*)d_in[0];
    const float* maskx = (const float*)d_in[1];
    const int*   pos   = (const int*)d_in[2];
    const int*   mgt   = (const int*)d_in[3];
    const float* aux   = (const float*)d_in[4];
    const float* taux  = (const float*)d_in[5];
    const float* sigma = (const float*)d_in[6];
    float* out = (float*)d_out;

    const int B        = in_sizes[0] / (SEQ_GEO * VOCAB);
    const int maskRows = B * SEQ_FULL;
    const int geoRows  = B * SEQ_GEO;

    const int nMaskJobs = maskRows / TILE_ROWS;   // 32-row tiles
    const int nGeoJobs  = geoRows / 96;           // 96-row (8-batch) jobs
    const int nJobs     = nMaskJobs + nGeoJobs;

    cudaFuncSetAttribute(fused_kernel,
                         cudaFuncAttributeMaxDynamicSharedMemorySize, DYN_SMEM);

    fused_kernel<<<GRID1, THREADS1, DYN_SMEM>>>(
        geo, maskx, pos, mgt, maskRows, B, nMaskJobs, nGeoJobs, nJobs,
        aux, taux, sigma, out);
}